// round 15
// baseline (speedup 1.0000x reference)
#include <cuda_runtime.h>

#define NN   50000
#define EE   800000
#define FIN  128
#define FHID 256
#define FOUT 128
#define ETOT (EE + NN)
#define NBLK ((NN + 255) / 256)   // 196 scan blocks

// ---------------- device scratch (no allocations allowed) ----------------
__device__ int   g_is64;
__device__ int   g_ei[2 * EE];               // decoded edge_index (int32)
__device__ int   g_deg[NN];
__device__ int   g_bsum[NBLK];
__device__ int   g_boff[NBLK];
__device__ int   g_rowptr[NN + 1];
__device__ int   g_cursor[NN];
__device__ int   g_col[ETOT];
__device__ float g_w[ETOT];
__device__ float g_dis[NN];
__device__ float g_agg1[(size_t)NN * FIN];   // 25.6 MB
__device__ float g_h1[(size_t)NN * FHID];    // 51.2 MB
__device__ float g_g2[(size_t)NN * FOUT];    // 25.6 MB

// ---------------- tf32 helpers ----------------
__device__ __forceinline__ unsigned f2tf32(float f) {
    unsigned r;
    asm("cvt.rna.tf32.f32 %0, %1;" : "=r"(r) : "f"(f));
    return r;
}
__device__ __forceinline__ void mma_tf32(float c[4], const unsigned a[4], const unsigned b[2]) {
    asm volatile(
        "mma.sync.aligned.m16n8k8.row.col.f32.tf32.tf32.f32 "
        "{%0,%1,%2,%3}, {%4,%5,%6,%7}, {%8,%9}, {%0,%1,%2,%3};"
        : "+f"(c[0]), "+f"(c[1]), "+f"(c[2]), "+f"(c[3])
        : "r"(a[0]), "r"(a[1]), "r"(a[2]), "r"(a[3]), "r"(b[0]), "r"(b[1]));
}

// ---------------- edge_index dtype detection + decode ----------------
__global__ void k_detect(const int* __restrict__ ei_raw) {
    if (threadIdx.x == 0) {
        int is64 = 1;
        for (int i = 1; i < 64; i += 2)
            if (ei_raw[i] != 0) { is64 = 0; break; }
        g_is64 = is64;
    }
}

__global__ void k_deg_init() {
    int i = blockIdx.x * blockDim.x + threadIdx.x;
    if (i < NN) g_deg[i] = 1;  // self-loop
}

// decode + FUSED dst-degree count (g_deg pre-initialized to 1 by k_deg_init)
__global__ void k_decode(const int* __restrict__ ei_raw) {
    int e = blockIdx.x * blockDim.x + threadIdx.x;
    if (e >= 2 * EE) return;
    int v = g_is64 ? ei_raw[2 * e] : ei_raw[e];
    v = min(max(v, 0), NN - 1);   // defensive clamp
    g_ei[e] = v;
    if (e >= EE) atomicAdd(&g_deg[v], 1);   // dst half
}

// ---- 3-phase parallel exclusive scan of g_deg ----
__global__ void k_bsum() {
    __shared__ int sh[256];
    int t = threadIdx.x;
    int i = blockIdx.x * 256 + t;
    int d = (i < NN) ? g_deg[i] : 0;
    sh[t] = d;
    __syncthreads();
    for (int off = 128; off > 0; off >>= 1) {
        if (t < off) sh[t] += sh[t + off];
        __syncthreads();
    }
    if (t == 0) g_bsum[blockIdx.x] = sh[0];
}

__global__ void k_bscan() {   // 1 block, 256 threads, scans NBLK block sums
    __shared__ int sh[256];
    int t = threadIdx.x;
    int v = (t < NBLK) ? g_bsum[t] : 0;
    sh[t] = v;
    __syncthreads();
    for (int off = 1; off < 256; off <<= 1) {
        int u = (t >= off) ? sh[t - off] : 0;
        __syncthreads();
        sh[t] += u;
        __syncthreads();
    }
    if (t < NBLK) g_boff[t] = sh[t] - v;   // exclusive
}

__global__ void k_emit() {
    __shared__ int sh[256];
    int t = threadIdx.x;
    int i = blockIdx.x * 256 + t;
    int d = (i < NN) ? g_deg[i] : 0;
    sh[t] = d;
    __syncthreads();
    for (int off = 1; off < 256; off <<= 1) {
        int u = (t >= off) ? sh[t - off] : 0;
        __syncthreads();
        sh[t] += u;
        __syncthreads();
    }
    int pref = g_boff[blockIdx.x] + sh[t] - d;   // exclusive prefix
    if (i < NN) {
        g_rowptr[i] = pref;
        g_cursor[i] = pref;
        g_dis[i]    = rsqrtf((float)d);
        if (i == NN - 1) g_rowptr[NN] = pref + d;
    }
}

__global__ void k_fill() {
    int e = blockIdx.x * blockDim.x + threadIdx.x;
    if (e >= ETOT) return;
    int s, d;
    if (e < EE) { s = g_ei[e]; d = g_ei[EE + e]; }
    else        { s = d = e - EE; }            // self-loop edges
    int pos = atomicAdd(&g_cursor[d], 1);
    g_col[pos] = s;
    g_w[pos]   = g_dis[s] * g_dis[d];
}

// ---------------- SpMM: out[r,:] = sum_e w[e] * in[col[e],:]  (F = 128) -------------
template <int LAYER>
__global__ void k_spmm128(const float* __restrict__ xin, float* __restrict__ xout,
                          const float* __restrict__ bias) {
    const float* in  = (LAYER == 1) ? xin : (const float*)g_g2;
    float*       out = (LAYER == 1) ? (float*)g_agg1 : xout;

    int warp = (blockIdx.x * blockDim.x + threadIdx.x) >> 5;
    int lane = threadIdx.x & 31;
    if (warp >= NN) return;
    int start = g_rowptr[warp];
    int end   = g_rowptr[warp + 1];
    const float4* in4 = (const float4*)in;
    float4 acc = make_float4(0.f, 0.f, 0.f, 0.f);

    for (int e0 = start; e0 < end; e0 += 32) {
        int e = e0 + lane;
        int   c  = 0;
        float wv = 0.f;
        if (e < end) { c = g_col[e]; wv = g_w[e]; }
        int cnt = min(32, end - e0);
        for (int j = 0; j < cnt; j++) {
            int   cj = __shfl_sync(0xffffffffu, c,  j);
            float wj = __shfl_sync(0xffffffffu, wv, j);
            float4 v = __ldg(&in4[(size_t)cj * 32 + lane]);
            acc.x = fmaf(wj, v.x, acc.x);
            acc.y = fmaf(wj, v.y, acc.y);
            acc.z = fmaf(wj, v.z, acc.z);
            acc.w = fmaf(wj, v.w, acc.w);
        }
    }
    if (LAYER == 2) {  // fuse bias + relu
        float4 b = ((const float4*)bias)[lane];
        acc.x = fmaxf(acc.x + b.x, 0.f);
        acc.y = fmaxf(acc.y + b.y, 0.f);
        acc.z = fmaxf(acc.z + b.z, 0.f);
        acc.w = fmaxf(acc.w + b.w, 0.f);
    }
    ((float4*)out)[(size_t)warp * 32 + lane] = acc;
}

// ---------------- tf32 tensor-core GEMM with register-prefetch pipeline -------------
// Block 128x64, BK=32, 256 threads = 8 warps (4M x 2N), warp tile 32x32.
// mma.m16n8k8 tf32; fp32 accumulate. A pad 36 / B pad 72 -> conflict-free frags.
// Global loads for tile kt+1 are issued into registers BEFORE computing tile kt.
template <int LAYER, int K, int NCOL>
__global__ __launch_bounds__(256) void k_gemm_tc(
    const float* __restrict__ B, const float* __restrict__ bias) {
    const float* A = (LAYER == 1) ? (const float*)g_agg1 : (const float*)g_h1;
    float*       C = (LAYER == 1) ? (float*)g_h1 : (float*)g_g2;
    const int M = NN;
    const int NT = K / 32;

    __shared__ unsigned As[128][36];   // 18.4 KB, tf32 bits
    __shared__ unsigned Bs[32][72];    //  9.2 KB

    int t    = threadIdx.x;
    int lane = t & 31;
    int w    = t >> 5;        // 0..7
    int wm   = w & 3;         // M group (4)
    int wn   = w >> 2;        // N group (2)
    int tg   = lane >> 2;     // 0..7
    int t4   = lane & 3;      // 0..3
    int m0 = blockIdx.y * 128;
    int n0 = blockIdx.x * 64;
    int m_w = wm * 32;
    int n_w = wn * 32;

    float acc[2][4][4];
#pragma unroll
    for (int mi = 0; mi < 2; mi++)
#pragma unroll
        for (int ni = 0; ni < 4; ni++)
#pragma unroll
            for (int r = 0; r < 4; r++) acc[mi][ni][r] = 0.f;

    // staging maps
    int a_m  = t >> 1;            // 0..127
    int a_kb = (t & 1) * 16;      // 0 or 16
    int b_k  = t >> 3;            // 0..31
    int b_n  = (t & 7) * 8;       // 0..56
    int arow = m0 + a_m;

    float4 pa[4], pb[2];

    // ---- prologue: load tile 0 into regs, store to smem ----
#pragma unroll
    for (int q = 0; q < 4; q++) {
        pa[q] = make_float4(0.f, 0.f, 0.f, 0.f);
        if (arow < M) pa[q] = *(const float4*)&A[(size_t)arow * K + a_kb + q * 4];
    }
#pragma unroll
    for (int q = 0; q < 2; q++)
        pb[q] = *(const float4*)&B[(size_t)b_k * NCOL + n0 + b_n + q * 4];

#pragma unroll
    for (int q = 0; q < 4; q++) {
        unsigned* dst = &As[a_m][a_kb + q * 4];
        dst[0] = f2tf32(pa[q].x); dst[1] = f2tf32(pa[q].y);
        dst[2] = f2tf32(pa[q].z); dst[3] = f2tf32(pa[q].w);
    }
#pragma unroll
    for (int q = 0; q < 2; q++) {
        unsigned* dst = &Bs[b_k][b_n + q * 4];
        dst[0] = f2tf32(pb[q].x); dst[1] = f2tf32(pb[q].y);
        dst[2] = f2tf32(pb[q].z); dst[3] = f2tf32(pb[q].w);
    }

    for (int kt = 0; kt < NT; kt++) {
        __syncthreads();   // smem tile kt ready
        // ---- issue global loads for tile kt+1 (latency hidden by compute) ----
        if (kt + 1 < NT) {
            int kk = (kt + 1) * 32;
#pragma unroll
            for (int q = 0; q < 4; q++) {
                pa[q] = make_float4(0.f, 0.f, 0.f, 0.f);
                if (arow < M)
                    pa[q] = *(const float4*)&A[(size_t)arow * K + kk + a_kb + q * 4];
            }
#pragma unroll
            for (int q = 0; q < 2; q++)
                pb[q] = *(const float4*)&B[(size_t)(kk + b_k) * NCOL + n0 + b_n + q * 4];
        }
        // ---- compute tile kt: 4 k-steps of 8 ----
#pragma unroll
        for (int ks = 0; ks < 4; ks++) {
            int k8 = ks * 8;
            unsigned af[2][4];
#pragma unroll
            for (int mi = 0; mi < 2; mi++) {
                int r = m_w + mi * 16 + tg;
                af[mi][0] = As[r][k8 + t4];
                af[mi][1] = As[r + 8][k8 + t4];
                af[mi][2] = As[r][k8 + t4 + 4];
                af[mi][3] = As[r + 8][k8 + t4 + 4];
            }
            unsigned bf[4][2];
#pragma unroll
            for (int ni = 0; ni < 4; ni++) {
                int cn = n_w + ni * 8 + tg;
                bf[ni][0] = Bs[k8 + t4][cn];
                bf[ni][1] = Bs[k8 + t4 + 4][cn];
            }
#pragma unroll
            for (int mi = 0; mi < 2; mi++)
#pragma unroll
                for (int ni = 0; ni < 4; ni++)
                    mma_tf32(acc[mi][ni], af[mi], bf[ni]);
        }
        __syncthreads();   // compute done; safe to overwrite smem
        // ---- store prefetched tile kt+1 to smem ----
        if (kt + 1 < NT) {
#pragma unroll
            for (int q = 0; q < 4; q++) {
                unsigned* dst = &As[a_m][a_kb + q * 4];
                dst[0] = f2tf32(pa[q].x); dst[1] = f2tf32(pa[q].y);
                dst[2] = f2tf32(pa[q].z); dst[3] = f2tf32(pa[q].w);
            }
#pragma unroll
            for (int q = 0; q < 2; q++) {
                unsigned* dst = &Bs[b_k][b_n + q * 4];
                dst[0] = f2tf32(pb[q].x); dst[1] = f2tf32(pb[q].y);
                dst[2] = f2tf32(pb[q].z); dst[3] = f2tf32(pb[q].w);
            }
        }
    }

    // ---- epilogue: bias+relu (layer 1), direct float2 stores ----
#pragma unroll
    for (int mi = 0; mi < 2; mi++) {
#pragma unroll
        for (int ni = 0; ni < 4; ni++) {
            int col  = n0 + n_w + ni * 8 + t4 * 2;
            float bx = 0.f, by = 0.f;
            if (LAYER == 1) {
                float2 bv = *(const float2*)&bias[col];
                bx = bv.x; by = bv.y;
            }
            float c0 = acc[mi][ni][0], c1 = acc[mi][ni][1];
            float c2 = acc[mi][ni][2], c3 = acc[mi][ni][3];
            if (LAYER == 1) {
                c0 = fmaxf(c0 + bx, 0.f); c1 = fmaxf(c1 + by, 0.f);
                c2 = fmaxf(c2 + bx, 0.f); c3 = fmaxf(c3 + by, 0.f);
            }
            int row0 = m0 + m_w + mi * 16 + tg;
            int row1 = row0 + 8;
            if (row0 < M) *(float2*)&C[(size_t)row0 * NCOL + col] = make_float2(c0, c1);
            if (row1 < M) *(float2*)&C[(size_t)row1 * NCOL + col] = make_float2(c2, c3);
        }
    }
}

// ---------------- launch (kernel launches ONLY — graph-capture safe) ----------------
extern "C" void kernel_launch(void* const* d_in, const int* in_sizes, int n_in,
                              void* d_out, int out_size) {
    const float* x   = (const float*)d_in[0];
    const int*   ei  = (const int*)d_in[1];   // raw words; dtype detected on device
    const float* W1  = (const float*)d_in[2];
    const float* b1  = (const float*)d_in[3];
    const float* W2  = (const float*)d_in[4];
    const float* b2  = (const float*)d_in[5];
    float*       out = (float*)d_out;

    // edge_index normalization + graph preprocessing
    k_detect<<<1, 32>>>(ei);
    k_deg_init<<<(NN + 255) / 256, 256>>>();
    k_decode<<<(2 * EE + 255) / 256, 256>>>(ei);   // decode + fused degree count
    k_bsum<<<NBLK, 256>>>();
    k_bscan<<<1, 256>>>();
    k_emit<<<NBLK, 256>>>();
    k_fill<<<(ETOT + 255) / 256, 256>>>();

    // layer 1: agg1 = A_hat * x ; h1 = relu(agg1 @ W1 + b1)
    k_spmm128<1><<<(NN * 32 + 255) / 256, 256>>>(x, nullptr, nullptr);
    dim3 g1(FHID / 64, (NN + 127) / 128);
    k_gemm_tc<1, FIN, FHID><<<g1, 256>>>(W1, b1);

    // layer 2: g2 = h1 @ W2 ; out = relu(A_hat * g2 + b2)
    dim3 g2d(FOUT / 64, (NN + 127) / 128);
    k_gemm_tc<2, FHID, FOUT><<<g2d, 256>>>(W2, nullptr);
    k_spmm128<2><<<(NN * 32 + 255) / 256, 256>>>(nullptr, out, b2);
}

// round 16
// speedup vs baseline: 1.0449x; 1.0449x over previous
#include <cuda_runtime.h>
#include <cuda_fp16.h>

#define NN   50000
#define EE   800000
#define FIN  128
#define FHID 256
#define FOUT 128
#define ETOT (EE + NN)
#define NBLK ((NN + 255) / 256)   // 196 scan blocks

// ---------------- device scratch (no allocations allowed) ----------------
__device__ int    g_is64;
__device__ int    g_ei[2 * EE];               // decoded edge_index (int32)
__device__ int    g_deg[NN];
__device__ int    g_bsum[NBLK];
__device__ int    g_boff[NBLK];
__device__ int    g_rowptr[NN + 1];
__device__ int    g_cursor[NN];
__device__ int    g_col[ETOT];
__device__ float  g_w[ETOT];
__device__ float  g_dis[NN];
__device__ __half g_xh[(size_t)NN * FIN];     // 12.8 MB fp16 gather payload L1
__device__ float  g_agg1[(size_t)NN * FIN];   // 25.6 MB
__device__ float  g_h1[(size_t)NN * FHID];    // 51.2 MB
__device__ __half g_g2h[(size_t)NN * FOUT];   // 12.8 MB fp16 gather payload L2

// ---------------- tf32 helpers ----------------
__device__ __forceinline__ unsigned f2tf32(float f) {
    unsigned r;
    asm("cvt.rna.tf32.f32 %0, %1;" : "=r"(r) : "f"(f));
    return r;
}
__device__ __forceinline__ void mma_tf32(float c[4], const unsigned a[4], const unsigned b[2]) {
    asm volatile(
        "mma.sync.aligned.m16n8k8.row.col.f32.tf32.tf32.f32 "
        "{%0,%1,%2,%3}, {%4,%5,%6,%7}, {%8,%9}, {%0,%1,%2,%3};"
        : "+f"(c[0]), "+f"(c[1]), "+f"(c[2]), "+f"(c[3])
        : "r"(a[0]), "r"(a[1]), "r"(a[2]), "r"(a[3]), "r"(b[0]), "r"(b[1]));
}

// ---------------- edge_index dtype detection + decode ----------------
__global__ void k_detect(const int* __restrict__ ei_raw) {
    if (threadIdx.x == 0) {
        int is64 = 1;
        for (int i = 1; i < 64; i += 2)
            if (ei_raw[i] != 0) { is64 = 0; break; }
        g_is64 = is64;
    }
}

__global__ void k_deg_init() {
    int i = blockIdx.x * blockDim.x + threadIdx.x;
    if (i < NN) g_deg[i] = 1;  // self-loop
}

// decode + FUSED dst-degree count (g_deg pre-initialized to 1 by k_deg_init)
__global__ void k_decode(const int* __restrict__ ei_raw) {
    int e = blockIdx.x * blockDim.x + threadIdx.x;
    if (e >= 2 * EE) return;
    int v = g_is64 ? ei_raw[2 * e] : ei_raw[e];
    v = min(max(v, 0), NN - 1);   // defensive clamp
    g_ei[e] = v;
    if (e >= EE) atomicAdd(&g_deg[v], 1);   // dst half
}

// ---- x -> fp16 payload conversion (one sequential pass) ----
__global__ void k_xtoh(const float* __restrict__ x) {
    int i = blockIdx.x * blockDim.x + threadIdx.x;   // 8 floats per thread
    const size_t TOT = (size_t)NN * FIN / 8;
    if (i >= TOT) return;
    const float4* x4 = (const float4*)x;
    float4 a = x4[2 * i];
    float4 b = x4[2 * i + 1];
    __half2 h[4];
    h[0] = __floats2half2_rn(a.x, a.y);
    h[1] = __floats2half2_rn(a.z, a.w);
    h[2] = __floats2half2_rn(b.x, b.y);
    h[3] = __floats2half2_rn(b.z, b.w);
    ((uint4*)g_xh)[i] = *(const uint4*)h;
}

// ---- 3-phase parallel exclusive scan of g_deg ----
__global__ void k_bsum() {
    __shared__ int sh[256];
    int t = threadIdx.x;
    int i = blockIdx.x * 256 + t;
    int d = (i < NN) ? g_deg[i] : 0;
    sh[t] = d;
    __syncthreads();
    for (int off = 128; off > 0; off >>= 1) {
        if (t < off) sh[t] += sh[t + off];
        __syncthreads();
    }
    if (t == 0) g_bsum[blockIdx.x] = sh[0];
}

__global__ void k_bscan() {   // 1 block, 256 threads, scans NBLK block sums
    __shared__ int sh[256];
    int t = threadIdx.x;
    int v = (t < NBLK) ? g_bsum[t] : 0;
    sh[t] = v;
    __syncthreads();
    for (int off = 1; off < 256; off <<= 1) {
        int u = (t >= off) ? sh[t - off] : 0;
        __syncthreads();
        sh[t] += u;
        __syncthreads();
    }
    if (t < NBLK) g_boff[t] = sh[t] - v;   // exclusive
}

__global__ void k_emit() {
    __shared__ int sh[256];
    int t = threadIdx.x;
    int i = blockIdx.x * 256 + t;
    int d = (i < NN) ? g_deg[i] : 0;
    sh[t] = d;
    __syncthreads();
    for (int off = 1; off < 256; off <<= 1) {
        int u = (t >= off) ? sh[t - off] : 0;
        __syncthreads();
        sh[t] += u;
        __syncthreads();
    }
    int pref = g_boff[blockIdx.x] + sh[t] - d;   // exclusive prefix
    if (i < NN) {
        g_rowptr[i] = pref;
        g_cursor[i] = pref;
        g_dis[i]    = rsqrtf((float)d);
        if (i == NN - 1) g_rowptr[NN] = pref + d;
    }
}

__global__ void k_fill() {
    int e = blockIdx.x * blockDim.x + threadIdx.x;
    if (e >= ETOT) return;
    int s, d;
    if (e < EE) { s = g_ei[e]; d = g_ei[EE + e]; }
    else        { s = d = e - EE; }            // self-loop edges
    int pos = atomicAdd(&g_cursor[d], 1);
    g_col[pos] = s;
    g_w[pos]   = g_dis[s] * g_dis[d];
}

// ---------------- SpMM (fp16 payload): out[r,:] = sum_e w[e] * in[col[e],:] --------
// one warp per row; per lane 4 feats = 2 half2 (8B load -> 256B/warp gather)
template <int LAYER>
__global__ void k_spmm128(const __half2* __restrict__ dummy_in,
                          float* __restrict__ xout, const float* __restrict__ bias) {
    const __half2* in2 = (LAYER == 1) ? (const __half2*)g_xh : (const __half2*)g_g2h;
    float*         out = (LAYER == 1) ? (float*)g_agg1 : xout;

    int warp = (blockIdx.x * blockDim.x + threadIdx.x) >> 5;
    int lane = threadIdx.x & 31;
    if (warp >= NN) return;
    int start = g_rowptr[warp];
    int end   = g_rowptr[warp + 1];
    float4 acc = make_float4(0.f, 0.f, 0.f, 0.f);

    for (int e0 = start; e0 < end; e0 += 32) {
        int e = e0 + lane;
        int   c  = 0;
        float wv = 0.f;
        if (e < end) { c = g_col[e]; wv = g_w[e]; }
        int cnt = min(32, end - e0);
        for (int j = 0; j < cnt; j++) {
            int   cj = __shfl_sync(0xffffffffu, c,  j);
            float wj = __shfl_sync(0xffffffffu, wv, j);
            // 64 half2 per row; this lane handles 2 of them (4 feats)
            const __half2* p = &in2[(size_t)cj * 64 + lane * 2];
            uint2 raw = __ldg((const uint2*)p);
            __half2 h0 = *(__half2*)&raw.x;
            __half2 h1 = *(__half2*)&raw.y;
            float2 v0 = __half22float2(h0);
            float2 v1 = __half22float2(h1);
            acc.x = fmaf(wj, v0.x, acc.x);
            acc.y = fmaf(wj, v0.y, acc.y);
            acc.z = fmaf(wj, v1.x, acc.z);
            acc.w = fmaf(wj, v1.y, acc.w);
        }
    }
    if (LAYER == 2) {  // fuse bias + relu
        const float4* b4 = (const float4*)bias;
        float4 b = b4[lane];
        acc.x = fmaxf(acc.x + b.x, 0.f);
        acc.y = fmaxf(acc.y + b.y, 0.f);
        acc.z = fmaxf(acc.z + b.z, 0.f);
        acc.w = fmaxf(acc.w + b.w, 0.f);
    }
    ((float4*)out)[(size_t)warp * 32 + lane] = acc;
}

// ---------------- tf32 tensor-core GEMM with register-prefetch pipeline -------------
// Block 128x64, BK=32, 256 threads = 8 warps (4M x 2N), warp tile 32x32.
// LAYER==2 writes fp16 (g_g2h) for the following gather; LAYER==1 writes fp32 h1.
template <int LAYER, int K, int NCOL>
__global__ __launch_bounds__(256) void k_gemm_tc(
    const float* __restrict__ B, const float* __restrict__ bias) {
    const float* A = (LAYER == 1) ? (const float*)g_agg1 : (const float*)g_h1;
    const int M = NN;
    const int NT = K / 32;

    __shared__ unsigned As[128][36];   // 18.4 KB, tf32 bits
    __shared__ unsigned Bs[32][72];    //  9.2 KB

    int t    = threadIdx.x;
    int lane = t & 31;
    int w    = t >> 5;        // 0..7
    int wm   = w & 3;         // M group (4)
    int wn   = w >> 2;        // N group (2)
    int tg   = lane >> 2;     // 0..7
    int t4   = lane & 3;      // 0..3
    int m0 = blockIdx.y * 128;
    int n0 = blockIdx.x * 64;
    int m_w = wm * 32;
    int n_w = wn * 32;

    float acc[2][4][4];
#pragma unroll
    for (int mi = 0; mi < 2; mi++)
#pragma unroll
        for (int ni = 0; ni < 4; ni++)
#pragma unroll
            for (int r = 0; r < 4; r++) acc[mi][ni][r] = 0.f;

    // staging maps
    int a_m  = t >> 1;            // 0..127
    int a_kb = (t & 1) * 16;      // 0 or 16
    int b_k  = t >> 3;            // 0..31
    int b_n  = (t & 7) * 8;       // 0..56
    int arow = m0 + a_m;

    float4 pa[4], pb[2];

    // ---- prologue: load tile 0 into regs, store to smem ----
#pragma unroll
    for (int q = 0; q < 4; q++) {
        pa[q] = make_float4(0.f, 0.f, 0.f, 0.f);
        if (arow < M) pa[q] = *(const float4*)&A[(size_t)arow * K + a_kb + q * 4];
    }
#pragma unroll
    for (int q = 0; q < 2; q++)
        pb[q] = *(const float4*)&B[(size_t)b_k * NCOL + n0 + b_n + q * 4];

#pragma unroll
    for (int q = 0; q < 4; q++) {
        unsigned* dst = &As[a_m][a_kb + q * 4];
        dst[0] = f2tf32(pa[q].x); dst[1] = f2tf32(pa[q].y);
        dst[2] = f2tf32(pa[q].z); dst[3] = f2tf32(pa[q].w);
    }
#pragma unroll
    for (int q = 0; q < 2; q++) {
        unsigned* dst = &Bs[b_k][b_n + q * 4];
        dst[0] = f2tf32(pb[q].x); dst[1] = f2tf32(pb[q].y);
        dst[2] = f2tf32(pb[q].z); dst[3] = f2tf32(pb[q].w);
    }

    for (int kt = 0; kt < NT; kt++) {
        __syncthreads();   // smem tile kt ready
        // ---- issue global loads for tile kt+1 (latency hidden by compute) ----
        if (kt + 1 < NT) {
            int kk = (kt + 1) * 32;
#pragma unroll
            for (int q = 0; q < 4; q++) {
                pa[q] = make_float4(0.f, 0.f, 0.f, 0.f);
                if (arow < M)
                    pa[q] = *(const float4*)&A[(size_t)arow * K + kk + a_kb + q * 4];
            }
#pragma unroll
            for (int q = 0; q < 2; q++)
                pb[q] = *(const float4*)&B[(size_t)(kk + b_k) * NCOL + n0 + b_n + q * 4];
        }
        // ---- compute tile kt: 4 k-steps of 8 ----
#pragma unroll
        for (int ks = 0; ks < 4; ks++) {
            int k8 = ks * 8;
            unsigned af[2][4];
#pragma unroll
            for (int mi = 0; mi < 2; mi++) {
                int r = m_w + mi * 16 + tg;
                af[mi][0] = As[r][k8 + t4];
                af[mi][1] = As[r + 8][k8 + t4];
                af[mi][2] = As[r][k8 + t4 + 4];
                af[mi][3] = As[r + 8][k8 + t4 + 4];
            }
            unsigned bf[4][2];
#pragma unroll
            for (int ni = 0; ni < 4; ni++) {
                int cn = n_w + ni * 8 + tg;
                bf[ni][0] = Bs[k8 + t4][cn];
                bf[ni][1] = Bs[k8 + t4 + 4][cn];
            }
#pragma unroll
            for (int mi = 0; mi < 2; mi++)
#pragma unroll
                for (int ni = 0; ni < 4; ni++)
                    mma_tf32(acc[mi][ni], af[mi], bf[ni]);
        }
        __syncthreads();   // compute done; safe to overwrite smem
        // ---- store prefetched tile kt+1 to smem ----
        if (kt + 1 < NT) {
#pragma unroll
            for (int q = 0; q < 4; q++) {
                unsigned* dst = &As[a_m][a_kb + q * 4];
                dst[0] = f2tf32(pa[q].x); dst[1] = f2tf32(pa[q].y);
                dst[2] = f2tf32(pa[q].z); dst[3] = f2tf32(pa[q].w);
            }
#pragma unroll
            for (int q = 0; q < 2; q++) {
                unsigned* dst = &Bs[b_k][b_n + q * 4];
                dst[0] = f2tf32(pb[q].x); dst[1] = f2tf32(pb[q].y);
                dst[2] = f2tf32(pb[q].z); dst[3] = f2tf32(pb[q].w);
            }
        }
    }

    // ---- epilogue ----
#pragma unroll
    for (int mi = 0; mi < 2; mi++) {
#pragma unroll
        for (int ni = 0; ni < 4; ni++) {
            int col  = n0 + n_w + ni * 8 + t4 * 2;
            float c0 = acc[mi][ni][0], c1 = acc[mi][ni][1];
            float c2 = acc[mi][ni][2], c3 = acc[mi][ni][3];
            int row0 = m0 + m_w + mi * 16 + tg;
            int row1 = row0 + 8;
            if (LAYER == 1) {   // bias + relu, fp32 out (h1)
                float2 bv = *(const float2*)&bias[col];
                c0 = fmaxf(c0 + bv.x, 0.f); c1 = fmaxf(c1 + bv.y, 0.f);
                c2 = fmaxf(c2 + bv.x, 0.f); c3 = fmaxf(c3 + bv.y, 0.f);
                float* C = (float*)g_h1;
                if (row0 < M) *(float2*)&C[(size_t)row0 * NCOL + col] = make_float2(c0, c1);
                if (row1 < M) *(float2*)&C[(size_t)row1 * NCOL + col] = make_float2(c2, c3);
            } else {            // fp16 out (g2 gather payload)
                __half2* C = (__half2*)g_g2h;
                if (row0 < M) C[((size_t)row0 * NCOL + col) / 2] = __floats2half2_rn(c0, c1);
                if (row1 < M) C[((size_t)row1 * NCOL + col) / 2] = __floats2half2_rn(c2, c3);
            }
        }
    }
}

// ---------------- launch (kernel launches ONLY — graph-capture safe) ----------------
extern "C" void kernel_launch(void* const* d_in, const int* in_sizes, int n_in,
                              void* d_out, int out_size) {
    const float* x   = (const float*)d_in[0];
    const int*   ei  = (const int*)d_in[1];   // raw words; dtype detected on device
    const float* W1  = (const float*)d_in[2];
    const float* b1  = (const float*)d_in[3];
    const float* W2  = (const float*)d_in[4];
    const float* b2  = (const float*)d_in[5];
    float*       out = (float*)d_out;

    // edge_index normalization + graph preprocessing
    k_detect<<<1, 32>>>(ei);
    k_deg_init<<<(NN + 255) / 256, 256>>>();
    k_decode<<<(2 * EE + 255) / 256, 256>>>(ei);   // decode + fused degree count
    k_xtoh<<<(NN * FIN / 8 + 255) / 256, 256>>>(x);
    k_bsum<<<NBLK, 256>>>();
    k_bscan<<<1, 256>>>();
    k_emit<<<NBLK, 256>>>();
    k_fill<<<(ETOT + 255) / 256, 256>>>();

    // layer 1: agg1 = A_hat * xh ; h1 = relu(agg1 @ W1 + b1)
    k_spmm128<1><<<(NN * 32 + 255) / 256, 256>>>(nullptr, nullptr, nullptr);
    dim3 g1(FHID / 64, (NN + 127) / 128);
    k_gemm_tc<1, FIN, FHID><<<g1, 256>>>(W1, b1);

    // layer 2: g2h = fp16(h1 @ W2) ; out = relu(A_hat * g2h + b2)
    dim3 g2d(FOUT / 64, (NN + 127) / 128);
    k_gemm_tc<2, FHID, FOUT><<<g2d, 256>>>(W2, nullptr);
    k_spmm128<2><<<(NN * 32 + 255) / 256, 256>>>(nullptr, out, b2);
}